// round 1
// baseline (speedup 1.0000x reference)
#include <cuda_runtime.h>

#define NB 2
#define NT 2048
#define ND 1024
#define NH 16
#define NHD 64
#define NM (NB * NT) /* 4096 rows */

// Scratch (device globals: allocation-free per harness rules)
__device__ float g_q[(size_t)NB * NH * NT * NHD];
__device__ float g_k[(size_t)NB * NH * NT * NHD];
__device__ float g_v[(size_t)NB * NH * NT * NHD];
__device__ float g_y[(size_t)NM * ND];

// ---------------------------------------------------------------------------
// Tiled SGEMM: C[m,n] = sum_k A[m,k] * W[n,k] + bias[n]
// 128x128 tile, K-step 8, 256 threads, 8x8 per-thread microtile.
// HEADS=true: blockIdx.z selects (Wq,Wk,Wv), output scattered to [B,H,T,HD].
// HEADS=false: A = g_y, output plain row-major [M,N] (final projection).
// ---------------------------------------------------------------------------
template <bool HEADS>
__global__ __launch_bounds__(256, 2)
void gemm_kernel(const float* __restrict__ A,
                 const float* __restrict__ W0, const float* __restrict__ B0,
                 const float* __restrict__ W1, const float* __restrict__ B1,
                 const float* __restrict__ W2, const float* __restrict__ B2,
                 float* __restrict__ Cplain)
{
    const float* W;
    const float* bias;
    float* outq = nullptr;
    if (HEADS) {
        int z = blockIdx.z;
        W    = (z == 0) ? W0 : (z == 1) ? W1 : W2;
        bias = (z == 0) ? B0 : (z == 1) ? B1 : B2;
        outq = (z == 0) ? g_q : (z == 1) ? g_k : g_v;
    } else {
        W = W0; bias = B0;
    }
    const float* Ap = HEADS ? A : g_y;

    __shared__ float As[8][128];
    __shared__ float Bs[8][128];

    const int tid = threadIdx.x;
    const int m0 = blockIdx.y * 128;
    const int n0 = blockIdx.x * 128;
    const int lr = tid >> 1;          // 0..127: tile row loaded by this thread
    const int lc = (tid & 1) * 4;     // 0 or 4 within k-step of 8
    const int mr = (tid >> 4) * 8;    // microtile row base
    const int nr = (tid & 15) * 8;    // microtile col base

    float acc[8][8];
#pragma unroll
    for (int i = 0; i < 8; i++)
#pragma unroll
        for (int j = 0; j < 8; j++) acc[i][j] = 0.f;

    const float* aPtr = Ap + (size_t)(m0 + lr) * ND + lc;
    const float* wPtr = W  + (size_t)(n0 + lr) * ND + lc;

    for (int k0 = 0; k0 < ND; k0 += 8) {
        float4 av = *(const float4*)(aPtr + k0);
        float4 wv = *(const float4*)(wPtr + k0);
        __syncthreads();   // previous iteration's compute done before overwrite
        As[lc + 0][lr] = av.x; As[lc + 1][lr] = av.y;
        As[lc + 2][lr] = av.z; As[lc + 3][lr] = av.w;
        Bs[lc + 0][lr] = wv.x; Bs[lc + 1][lr] = wv.y;
        Bs[lc + 2][lr] = wv.z; Bs[lc + 3][lr] = wv.w;
        __syncthreads();
#pragma unroll
        for (int kk = 0; kk < 8; kk++) {
            float ra[8], rb[8];
            *(float4*)&ra[0] = *(const float4*)&As[kk][mr];
            *(float4*)&ra[4] = *(const float4*)&As[kk][mr + 4];
            *(float4*)&rb[0] = *(const float4*)&Bs[kk][nr];
            *(float4*)&rb[4] = *(const float4*)&Bs[kk][nr + 4];
#pragma unroll
            for (int i = 0; i < 8; i++)
#pragma unroll
                for (int j = 0; j < 8; j++)
                    acc[i][j] += ra[i] * rb[j];
        }
    }

#pragma unroll
    for (int i = 0; i < 8; i++) {
        int m = m0 + mr + i;
#pragma unroll
        for (int j = 0; j < 8; j++) {
            int n = n0 + nr + j;
            float val = acc[i][j] + bias[n];
            if (HEADS) {
                int bb = m >> 11;           // m / 2048
                int t  = m & (NT - 1);
                int h  = n >> 6;            // n / 64
                int hd = n & (NHD - 1);
                outq[(((size_t)bb * NH + h) * NT + t) * NHD + hd] = val;
            } else {
                Cplain[(size_t)m * ND + n] = val;
            }
        }
    }
}

// ---------------------------------------------------------------------------
// fp32 flash attention, causal. One thread owns one query row (128 q rows /
// CTA), 64-key K/V tiles in smem, online softmax in 16-key register chunks.
// ---------------------------------------------------------------------------
__global__ __launch_bounds__(128)
void attn_kernel()
{
    const int bh  = blockIdx.y;            // b*NH + h
    const int q0  = blockIdx.x * 128;
    const int tid = threadIdx.x;
    const int qg  = q0 + tid;              // global query index

    const float* Qb = g_q + (size_t)bh * NT * NHD;
    const float* Kb = g_k + (size_t)bh * NT * NHD;
    const float* Vb = g_v + (size_t)bh * NT * NHD;

    __shared__ float Ks[64][NHD];
    __shared__ float Vs[64][NHD];

    float qreg[NHD];
#pragma unroll
    for (int d = 0; d < NHD; d += 4) {
        float4 t = *(const float4*)(Qb + (size_t)qg * NHD + d);
        qreg[d] = t.x; qreg[d + 1] = t.y; qreg[d + 2] = t.z; qreg[d + 3] = t.w;
    }

    float acc[NHD];
#pragma unroll
    for (int d = 0; d < NHD; d++) acc[d] = 0.f;
    float mval = -1e30f, lval = 0.f;

    const int ktiles = blockIdx.x * 2 + 2;  // covers keys [0, q0+128)
    for (int kt = 0; kt < ktiles; kt++) {
        const int kbase = kt * 64;
        __syncthreads();                    // finish compute before reload
#pragma unroll
        for (int i = 0; i < 8; i++) {       // 1024 float4 slots per tile
            int idx = tid + i * 128;
            int row = idx >> 4;
            int col = (idx & 15) * 4;
            *(float4*)&Ks[row][col] =
                *(const float4*)(Kb + (size_t)(kbase + row) * NHD + col);
            *(float4*)&Vs[row][col] =
                *(const float4*)(Vb + (size_t)(kbase + row) * NHD + col);
        }
        __syncthreads();

#pragma unroll 1
        for (int c = 0; c < 4; c++) {       // 4 chunks of 16 keys
            float sreg[16];
            float tmax = -1e30f;
#pragma unroll
            for (int jj = 0; jj < 16; jj++) {
                int kj = c * 16 + jj;
                float s0 = 0.f, s1 = 0.f, s2 = 0.f, s3 = 0.f;
#pragma unroll
                for (int d = 0; d < NHD; d += 4) {
                    float4 kv = *(const float4*)&Ks[kj][d];
                    s0 += qreg[d]     * kv.x;
                    s1 += qreg[d + 1] * kv.y;
                    s2 += qreg[d + 2] * kv.z;
                    s3 += qreg[d + 3] * kv.w;
                }
                float s = ((s0 + s1) + (s2 + s3)) * 0.125f;  // 1/sqrt(64)
                s = (kbase + kj > qg) ? -1e30f : s;          // causal mask
                sreg[jj] = s;
                tmax = fmaxf(tmax, s);
            }
            float mnew = fmaxf(mval, tmax);
            float corr = __expf(mval - mnew);
            lval *= corr;
#pragma unroll
            for (int d = 0; d < NHD; d++) acc[d] *= corr;
#pragma unroll
            for (int jj = 0; jj < 16; jj++) {
                int kj = c * 16 + jj;
                float p = __expf(sreg[jj] - mnew);
                lval += p;
#pragma unroll
                for (int d = 0; d < NHD; d += 4) {
                    float4 vv = *(const float4*)&Vs[kj][d];
                    acc[d]     += p * vv.x;
                    acc[d + 1] += p * vv.y;
                    acc[d + 2] += p * vv.z;
                    acc[d + 3] += p * vv.w;
                }
            }
            mval = mnew;
        }
    }

    const int b = bh >> 4, h = bh & (NH - 1);
    float inv = 1.f / lval;
    float* yrow = g_y + ((size_t)b * NT + qg) * ND + h * NHD;
#pragma unroll
    for (int d = 0; d < NHD; d += 4) {
        float4 o = make_float4(acc[d] * inv, acc[d + 1] * inv,
                               acc[d + 2] * inv, acc[d + 3] * inv);
        *(float4*)(yrow + d) = o;
    }
}

// ---------------------------------------------------------------------------
extern "C" void kernel_launch(void* const* d_in, const int* in_sizes, int n_in,
                              void* d_out, int out_size)
{
    const float* x  = (const float*)d_in[0];
    const float* Wq = (const float*)d_in[1];
    const float* bq = (const float*)d_in[2];
    const float* Wk = (const float*)d_in[3];
    const float* bk = (const float*)d_in[4];
    const float* Wv = (const float*)d_in[5];
    const float* bv = (const float*)d_in[6];
    const float* Wp = (const float*)d_in[7];
    const float* bp = (const float*)d_in[8];
    float* out = (float*)d_out;

    dim3 gq(ND / 128, NM / 128, 3);   // 8 x 32 x 3
    gemm_kernel<true><<<gq, 256>>>(x, Wq, bq, Wk, bk, Wv, bv, nullptr);

    dim3 ga(NT / 128, NB * NH);       // 16 x 32
    attn_kernel<<<ga, 128>>>();

    dim3 gp(ND / 128, NM / 128, 1);   // 8 x 32
    gemm_kernel<false><<<gp, 256>>>(nullptr, Wp, bp, nullptr, nullptr,
                                    nullptr, nullptr, out);
}

// round 3
// speedup vs baseline: 1.4512x; 1.4512x over previous
#include <cuda_runtime.h>
#include <cstdint>

#define NB 2
#define NT 2048
#define ND 1024
#define NH 16
#define NHD 64
#define NM (NB * NT) /* 4096 rows */

// Scratch (device globals: allocation-free per harness rules)
__device__ float g_q[(size_t)NB * NH * NT * NHD];
__device__ float g_k[(size_t)NB * NH * NT * NHD];
__device__ float g_v[(size_t)NB * NH * NT * NHD];
__device__ float g_y[(size_t)NM * ND];

// ---------------------------------------------------------------------------
// tf32 helpers
// ---------------------------------------------------------------------------
__device__ __forceinline__ uint32_t f2tf32(float x) {
    uint32_t r;
    asm("cvt.rna.tf32.f32 %0, %1;" : "=r"(r) : "f"(x));
    return r;
}

__device__ __forceinline__ void mma_tf32(float* c, const uint32_t* a,
                                         const uint32_t* b) {
    asm volatile(
        "mma.sync.aligned.m16n8k8.row.col.f32.tf32.tf32.f32 "
        "{%0,%1,%2,%3}, {%4,%5,%6,%7}, {%8,%9}, {%0,%1,%2,%3};\n"
        : "+f"(c[0]), "+f"(c[1]), "+f"(c[2]), "+f"(c[3])
        : "r"(a[0]), "r"(a[1]), "r"(a[2]), "r"(a[3]), "r"(b[0]), "r"(b[1]));
}

// ---------------------------------------------------------------------------
// tf32 tensor-core GEMM: C[m,n] = sum_k A[m,k] * W[n,k] + bias[n]
// 128x128 tile, K-step 16, 256 threads (8 warps, 2x4), warp tile 64x32.
// HEADS=true: blockIdx.z selects (Wq,Wk,Wv), output scattered to [B,H,T,HD].
// HEADS=false: A = g_y, output plain row-major [M,N] (final projection).
// ---------------------------------------------------------------------------
#define BKP 20  /* padded K stride: conflict-free fragment loads */

template <bool HEADS>
__global__ __launch_bounds__(256, 2)
void gemm_kernel(const float* __restrict__ A,
                 const float* __restrict__ W0, const float* __restrict__ B0,
                 const float* __restrict__ W1, const float* __restrict__ B1,
                 const float* __restrict__ W2, const float* __restrict__ B2,
                 float* __restrict__ Cplain)
{
    const float* W;
    const float* bias;
    float* outq = nullptr;
    if (HEADS) {
        int z = blockIdx.z;
        W    = (z == 0) ? W0 : (z == 1) ? W1 : W2;
        bias = (z == 0) ? B0 : (z == 1) ? B1 : B2;
        outq = (z == 0) ? g_q : (z == 1) ? g_k : g_v;
    } else {
        W = W0; bias = B0;
    }
    const float* Ap = HEADS ? A : g_y;

    __shared__ uint32_t As[128][BKP];
    __shared__ uint32_t Bs[128][BKP];

    const int tid  = threadIdx.x;
    const int lane = tid & 31;
    const int wid  = tid >> 5;
    const int m0 = blockIdx.y * 128;
    const int n0 = blockIdx.x * 128;
    const int warp_m = (wid >> 2) * 64;   // 0 or 64
    const int warp_n = (wid & 3) * 32;    // 0,32,64,96

    // global->smem mapping: 512 float4 per tile, 2 per thread
    const int r0 = tid >> 2;              // rows 0..63
    const int c4 = (tid & 3) * 4;         // col 0,4,8,12

    float acc[4][4][4];
#pragma unroll
    for (int mi = 0; mi < 4; mi++)
#pragma unroll
        for (int ni = 0; ni < 4; ni++)
#pragma unroll
            for (int r = 0; r < 4; r++) acc[mi][ni][r] = 0.f;

    const float* aBase = Ap + (size_t)m0 * ND;
    const float* wBase = W  + (size_t)n0 * ND;

    // prefetch tile k0=0
    float4 pa0 = *(const float4*)(aBase + (size_t)r0 * ND + c4);
    float4 pa1 = *(const float4*)(aBase + (size_t)(r0 + 64) * ND + c4);
    float4 pb0 = *(const float4*)(wBase + (size_t)r0 * ND + c4);
    float4 pb1 = *(const float4*)(wBase + (size_t)(r0 + 64) * ND + c4);

    for (int k0 = 0; k0 < ND; k0 += 16) {
        __syncthreads();   // previous compute done before overwrite
        {
            uint4 u;
            u.x = f2tf32(pa0.x); u.y = f2tf32(pa0.y);
            u.z = f2tf32(pa0.z); u.w = f2tf32(pa0.w);
            *(uint4*)&As[r0][c4] = u;
            u.x = f2tf32(pa1.x); u.y = f2tf32(pa1.y);
            u.z = f2tf32(pa1.z); u.w = f2tf32(pa1.w);
            *(uint4*)&As[r0 + 64][c4] = u;
            u.x = f2tf32(pb0.x); u.y = f2tf32(pb0.y);
            u.z = f2tf32(pb0.z); u.w = f2tf32(pb0.w);
            *(uint4*)&Bs[r0][c4] = u;
            u.x = f2tf32(pb1.x); u.y = f2tf32(pb1.y);
            u.z = f2tf32(pb1.z); u.w = f2tf32(pb1.w);
            *(uint4*)&Bs[r0 + 64][c4] = u;
        }
        __syncthreads();

        if (k0 + 16 < ND) {
            const int kn = k0 + 16;
            pa0 = *(const float4*)(aBase + (size_t)r0 * ND + kn + c4);
            pa1 = *(const float4*)(aBase + (size_t)(r0 + 64) * ND + kn + c4);
            pb0 = *(const float4*)(wBase + (size_t)r0 * ND + kn + c4);
            pb1 = *(const float4*)(wBase + (size_t)(r0 + 64) * ND + kn + c4);
        }

#pragma unroll
        for (int t = 0; t < 2; t++) {
            const int kk = t * 8 + (lane & 3);
            uint32_t afr[4][4], bfr[4][2];
#pragma unroll
            for (int mi = 0; mi < 4; mi++) {
                int r = warp_m + mi * 16 + (lane >> 2);
                afr[mi][0] = As[r][kk];
                afr[mi][1] = As[r + 8][kk];
                afr[mi][2] = As[r][kk + 4];
                afr[mi][3] = As[r + 8][kk + 4];
            }
#pragma unroll
            for (int ni = 0; ni < 4; ni++) {
                int c = warp_n + ni * 8 + (lane >> 2);
                bfr[ni][0] = Bs[c][kk];
                bfr[ni][1] = Bs[c][kk + 4];
            }
#pragma unroll
            for (int mi = 0; mi < 4; mi++)
#pragma unroll
                for (int ni = 0; ni < 4; ni++)
                    mma_tf32(acc[mi][ni], afr[mi], bfr[ni]);
        }
    }

    // epilogue: c0,c1 at (row, 2c),(row, 2c+1); c2,c3 at (row+8, ...)
#pragma unroll
    for (int mi = 0; mi < 4; mi++) {
#pragma unroll
        for (int ni = 0; ni < 4; ni++) {
#pragma unroll
            for (int half = 0; half < 2; half++) {
                int m = m0 + warp_m + mi * 16 + (lane >> 2) + half * 8;
                int nA = n0 + warp_n + ni * 8 + 2 * (lane & 3);
                float v0 = acc[mi][ni][half * 2 + 0] + bias[nA];
                float v1 = acc[mi][ni][half * 2 + 1] + bias[nA + 1];
                if (HEADS) {
                    int bb = m >> 11;            // m / 2048
                    int tt = m & (NT - 1);
                    int h  = nA >> 6;            // n / 64 (pair stays in head)
                    int hd = nA & (NHD - 1);
                    float* dst = outq +
                        (((size_t)bb * NH + h) * NT + tt) * NHD + hd;
                    dst[0] = v0; dst[1] = v1;
                } else {
                    float* dst = Cplain + (size_t)m * ND + nA;
                    dst[0] = v0; dst[1] = v1;
                }
            }
        }
    }
}

// ---------------------------------------------------------------------------
// fp32 flash attention, causal (unchanged from R1 — converts next round).
// ---------------------------------------------------------------------------
__global__ __launch_bounds__(128)
void attn_kernel()
{
    const int bh  = blockIdx.y;            // b*NH + h
    const int q0  = blockIdx.x * 128;
    const int tid = threadIdx.x;
    const int qg  = q0 + tid;              // global query index

    const float* Qb = g_q + (size_t)bh * NT * NHD;
    const float* Kb = g_k + (size_t)bh * NT * NHD;
    const float* Vb = g_v + (size_t)bh * NT * NHD;

    __shared__ float Ks[64][NHD];
    __shared__ float Vs[64][NHD];

    float qreg[NHD];
#pragma unroll
    for (int d = 0; d < NHD; d += 4) {
        float4 t = *(const float4*)(Qb + (size_t)qg * NHD + d);
        qreg[d] = t.x; qreg[d + 1] = t.y; qreg[d + 2] = t.z; qreg[d + 3] = t.w;
    }

    float acc[NHD];
#pragma unroll
    for (int d = 0; d < NHD; d++) acc[d] = 0.f;
    float mval = -1e30f, lval = 0.f;

    const int ktiles = blockIdx.x * 2 + 2;  // covers keys [0, q0+128)
    for (int kt = 0; kt < ktiles; kt++) {
        const int kbase = kt * 64;
        __syncthreads();                    // finish compute before reload
#pragma unroll
        for (int i = 0; i < 8; i++) {       // 1024 float4 slots per tile
            int idx = tid + i * 128;
            int row = idx >> 4;
            int col = (idx & 15) * 4;
            *(float4*)&Ks[row][col] =
                *(const float4*)(Kb + (size_t)(kbase + row) * NHD + col);
            *(float4*)&Vs[row][col] =
                *(const float4*)(Vb + (size_t)(kbase + row) * NHD + col);
        }
        __syncthreads();

#pragma unroll 1
        for (int c = 0; c < 4; c++) {       // 4 chunks of 16 keys
            float sreg[16];
            float tmax = -1e30f;
#pragma unroll
            for (int jj = 0; jj < 16; jj++) {
                int kj = c * 16 + jj;
                float s0 = 0.f, s1 = 0.f, s2 = 0.f, s3 = 0.f;
#pragma unroll
                for (int d = 0; d < NHD; d += 4) {
                    float4 kv = *(const float4*)&Ks[kj][d];
                    s0 += qreg[d]     * kv.x;
                    s1 += qreg[d + 1] * kv.y;
                    s2 += qreg[d + 2] * kv.z;
                    s3 += qreg[d + 3] * kv.w;
                }
                float s = ((s0 + s1) + (s2 + s3)) * 0.125f;  // 1/sqrt(64)
                s = (kbase + kj > qg) ? -1e30f : s;          // causal mask
                sreg[jj] = s;
                tmax = fmaxf(tmax, s);
            }
            float mnew = fmaxf(mval, tmax);
            float corr = __expf(mval - mnew);
            lval *= corr;
#pragma unroll
            for (int d = 0; d < NHD; d++) acc[d] *= corr;
#pragma unroll
            for (int jj = 0; jj < 16; jj++) {
                int kj = c * 16 + jj;
                float p = __expf(sreg[jj] - mnew);
                lval += p;
#pragma unroll
                for (int d = 0; d < NHD; d += 4) {
                    float4 vv = *(const float4*)&Vs[kj][d];
                    acc[d]     += p * vv.x;
                    acc[d + 1] += p * vv.y;
                    acc[d + 2] += p * vv.z;
                    acc[d + 3] += p * vv.w;
                }
            }
            mval = mnew;
        }
    }

    const int b = bh >> 4, h = bh & (NH - 1);
    float inv = 1.f / lval;
    float* yrow = g_y + ((size_t)b * NT + qg) * ND + h * NHD;
#pragma unroll
    for (int d = 0; d < NHD; d += 4) {
        float4 o = make_float4(acc[d] * inv, acc[d + 1] * inv,
                               acc[d + 2] * inv, acc[d + 3] * inv);
        *(float4*)(yrow + d) = o;
    }
}

// ---------------------------------------------------------------------------
extern "C" void kernel_launch(void* const* d_in, const int* in_sizes, int n_in,
                              void* d_out, int out_size)
{
    const float* x  = (const float*)d_in[0];
    const float* Wq = (const float*)d_in[1];
    const float* bq = (const float*)d_in[2];
    const float* Wk = (const float*)d_in[3];
    const float* bk = (const float*)d_in[4];
    const float* Wv = (const float*)d_in[5];
    const float* bv = (const float*)d_in[6];
    const float* Wp = (const float*)d_in[7];
    const float* bp = (const float*)d_in[8];
    float* out = (float*)d_out;

    dim3 gq(ND / 128, NM / 128, 3);   // 8 x 32 x 3
    gemm_kernel<true><<<gq, 256>>>(x, Wq, bq, Wk, bk, Wv, bv, nullptr);

    dim3 ga(NT / 128, NB * NH);       // 16 x 32
    attn_kernel<<<ga, 128>>>();

    dim3 gp(ND / 128, NM / 128, 1);   // 8 x 32
    gemm_kernel<false><<<gp, 256>>>(nullptr, Wp, bp, nullptr, nullptr,
                                    nullptr, nullptr, out);
}

// round 5
// speedup vs baseline: 3.1530x; 2.1728x over previous
#include <cuda_runtime.h>
#include <cstdint>

#define NB 2
#define NT 2048
#define ND 1024
#define NH 16
#define NHD 64
#define NM (NB * NT) /* 4096 rows */

// Scratch (device globals: allocation-free per harness rules)
__device__ float g_q[(size_t)NB * NH * NT * NHD];
__device__ float g_k[(size_t)NB * NH * NT * NHD];
__device__ float g_v[(size_t)NB * NH * NT * NHD];
__device__ float g_y[(size_t)NM * ND];

// ---------------------------------------------------------------------------
// tf32 / math helpers
// ---------------------------------------------------------------------------
__device__ __forceinline__ uint32_t f2tf32(float x) {
    uint32_t r;
    asm("cvt.rna.tf32.f32 %0, %1;" : "=r"(r) : "f"(x));
    return r;
}

__device__ __forceinline__ float ex2(float x) {
    float y;
    asm("ex2.approx.ftz.f32 %0, %1;" : "=f"(y) : "f"(x));
    return y;
}

__device__ __forceinline__ void mma_tf32(float* c, const uint32_t* a,
                                         const uint32_t* b) {
    asm volatile(
        "mma.sync.aligned.m16n8k8.row.col.f32.tf32.tf32.f32 "
        "{%0,%1,%2,%3}, {%4,%5,%6,%7}, {%8,%9}, {%0,%1,%2,%3};\n"
        : "+f"(c[0]), "+f"(c[1]), "+f"(c[2]), "+f"(c[3])
        : "r"(a[0]), "r"(a[1]), "r"(a[2]), "r"(a[3]), "r"(b[0]), "r"(b[1]));
}

// ---------------------------------------------------------------------------
// tf32 tensor-core GEMM (unchanged from R3): C[m,n] = A[m,:]·W[n,:] + bias[n]
// ---------------------------------------------------------------------------
#define BKP 20

template <bool HEADS>
__global__ __launch_bounds__(256, 2)
void gemm_kernel(const float* __restrict__ A,
                 const float* __restrict__ W0, const float* __restrict__ B0,
                 const float* __restrict__ W1, const float* __restrict__ B1,
                 const float* __restrict__ W2, const float* __restrict__ B2,
                 float* __restrict__ Cplain)
{
    const float* W;
    const float* bias;
    float* outq = nullptr;
    if (HEADS) {
        int z = blockIdx.z;
        W    = (z == 0) ? W0 : (z == 1) ? W1 : W2;
        bias = (z == 0) ? B0 : (z == 1) ? B1 : B2;
        outq = (z == 0) ? g_q : (z == 1) ? g_k : g_v;
    } else {
        W = W0; bias = B0;
    }
    const float* Ap = HEADS ? A : g_y;

    __shared__ uint32_t As[128][BKP];
    __shared__ uint32_t Bs[128][BKP];

    const int tid  = threadIdx.x;
    const int lane = tid & 31;
    const int wid  = tid >> 5;
    const int m0 = blockIdx.y * 128;
    const int n0 = blockIdx.x * 128;
    const int warp_m = (wid >> 2) * 64;
    const int warp_n = (wid & 3) * 32;

    const int r0 = tid >> 2;
    const int c4 = (tid & 3) * 4;

    float acc[4][4][4];
#pragma unroll
    for (int mi = 0; mi < 4; mi++)
#pragma unroll
        for (int ni = 0; ni < 4; ni++)
#pragma unroll
            for (int r = 0; r < 4; r++) acc[mi][ni][r] = 0.f;

    const float* aBase = Ap + (size_t)m0 * ND;
    const float* wBase = W  + (size_t)n0 * ND;

    float4 pa0 = *(const float4*)(aBase + (size_t)r0 * ND + c4);
    float4 pa1 = *(const float4*)(aBase + (size_t)(r0 + 64) * ND + c4);
    float4 pb0 = *(const float4*)(wBase + (size_t)r0 * ND + c4);
    float4 pb1 = *(const float4*)(wBase + (size_t)(r0 + 64) * ND + c4);

    for (int k0 = 0; k0 < ND; k0 += 16) {
        __syncthreads();
        {
            uint4 u;
            u.x = f2tf32(pa0.x); u.y = f2tf32(pa0.y);
            u.z = f2tf32(pa0.z); u.w = f2tf32(pa0.w);
            *(uint4*)&As[r0][c4] = u;
            u.x = f2tf32(pa1.x); u.y = f2tf32(pa1.y);
            u.z = f2tf32(pa1.z); u.w = f2tf32(pa1.w);
            *(uint4*)&As[r0 + 64][c4] = u;
            u.x = f2tf32(pb0.x); u.y = f2tf32(pb0.y);
            u.z = f2tf32(pb0.z); u.w = f2tf32(pb0.w);
            *(uint4*)&Bs[r0][c4] = u;
            u.x = f2tf32(pb1.x); u.y = f2tf32(pb1.y);
            u.z = f2tf32(pb1.z); u.w = f2tf32(pb1.w);
            *(uint4*)&Bs[r0 + 64][c4] = u;
        }
        __syncthreads();

        if (k0 + 16 < ND) {
            const int kn = k0 + 16;
            pa0 = *(const float4*)(aBase + (size_t)r0 * ND + kn + c4);
            pa1 = *(const float4*)(aBase + (size_t)(r0 + 64) * ND + kn + c4);
            pb0 = *(const float4*)(wBase + (size_t)r0 * ND + kn + c4);
            pb1 = *(const float4*)(wBase + (size_t)(r0 + 64) * ND + kn + c4);
        }

#pragma unroll
        for (int t = 0; t < 2; t++) {
            const int kk = t * 8 + (lane & 3);
            uint32_t afr[4][4], bfr[4][2];
#pragma unroll
            for (int mi = 0; mi < 4; mi++) {
                int r = warp_m + mi * 16 + (lane >> 2);
                afr[mi][0] = As[r][kk];
                afr[mi][1] = As[r + 8][kk];
                afr[mi][2] = As[r][kk + 4];
                afr[mi][3] = As[r + 8][kk + 4];
            }
#pragma unroll
            for (int ni = 0; ni < 4; ni++) {
                int c = warp_n + ni * 8 + (lane >> 2);
                bfr[ni][0] = Bs[c][kk];
                bfr[ni][1] = Bs[c][kk + 4];
            }
#pragma unroll
            for (int mi = 0; mi < 4; mi++)
#pragma unroll
                for (int ni = 0; ni < 4; ni++)
                    mma_tf32(acc[mi][ni], afr[mi], bfr[ni]);
        }
    }

#pragma unroll
    for (int mi = 0; mi < 4; mi++) {
#pragma unroll
        for (int ni = 0; ni < 4; ni++) {
#pragma unroll
            for (int half = 0; half < 2; half++) {
                int m = m0 + warp_m + mi * 16 + (lane >> 2) + half * 8;
                int nA = n0 + warp_n + ni * 8 + 2 * (lane & 3);
                float v0 = acc[mi][ni][half * 2 + 0] + bias[nA];
                float v1 = acc[mi][ni][half * 2 + 1] + bias[nA + 1];
                if (HEADS) {
                    int bb = m >> 11;
                    int tt = m & (NT - 1);
                    int h  = nA >> 6;
                    int hd = nA & (NHD - 1);
                    float* dst = outq +
                        (((size_t)bb * NH + h) * NT + tt) * NHD + hd;
                    dst[0] = v0; dst[1] = v1;
                } else {
                    float* dst = Cplain + (size_t)m * ND + nA;
                    dst[0] = v0; dst[1] = v1;
                }
            }
        }
    }
}

// ---------------------------------------------------------------------------
// Tensor-core tf32 flash attention, causal.
// CTA: 128 q rows, 8 warps x 16 rows. 64-key K/V tiles in smem (natural
// [key][dim] layout, stride 72 words -> all fragment reads conflict-free).
// P round-trips through warp-private smem slab (syncwarp only).
// R5 fix: quad-reduce the softmax denominators l0/l1 (they are per-thread
// partials over columns 2c,2c+1 mod 8) before normalizing. Without it,
// early rows with fully-masked quad-lanes hit l=0 -> inv=inf -> 0*inf=NaN.
// ---------------------------------------------------------------------------
#define AST 72  /* smem row stride in words */
#define ATTN_SMEM ((64 + 64 + 128) * AST * 4)  /* 73728 B */

__global__ __launch_bounds__(256)
void attn_tc_kernel()
{
    extern __shared__ uint32_t smraw[];
    uint32_t (*Ks)[AST] = (uint32_t(*)[AST])smraw;
    uint32_t (*Vs)[AST] = (uint32_t(*)[AST])(smraw + 64 * AST);
    uint32_t (*Ps)[AST] = (uint32_t(*)[AST])(smraw + 128 * AST);

    const int bh   = blockIdx.y;
    const int q0   = blockIdx.x * 128;
    const int tid  = threadIdx.x;
    const int lane = tid & 31;
    const int warp = tid >> 5;
    const int r    = lane >> 2;    // 0..7
    const int c    = lane & 3;     // 0..3
    const int w16  = warp * 16;

    const float* Qb = g_q + (size_t)bh * NT * NHD;
    const float* Kb = g_k + (size_t)bh * NT * NHD;
    const float* Vb = g_v + (size_t)bh * NT * NHD;

    // ---- stage Q tile through Ps, pull A-fragments into registers ----
#pragma unroll
    for (int i = 0; i < 8; i++) {
        int idx = tid + i * 256;        // 0..2047
        int row = idx >> 4;             // 0..127
        int c4  = (idx & 15) * 4;
        float4 v = *(const float4*)(Qb + (size_t)(q0 + row) * NHD + c4);
        uint4 u;
        u.x = f2tf32(v.x); u.y = f2tf32(v.y);
        u.z = f2tf32(v.z); u.w = f2tf32(v.w);
        *(uint4*)&Ps[row][c4] = u;
    }
    __syncthreads();

    uint32_t qf[8][4];
#pragma unroll
    for (int kc = 0; kc < 8; kc++) {
        qf[kc][0] = Ps[w16 + r][kc * 8 + c];
        qf[kc][1] = Ps[w16 + r + 8][kc * 8 + c];
        qf[kc][2] = Ps[w16 + r][kc * 8 + c + 4];
        qf[kc][3] = Ps[w16 + r + 8][kc * 8 + c + 4];
    }
    __syncthreads();

    float o[8][4];
#pragma unroll
    for (int nt = 0; nt < 8; nt++)
#pragma unroll
        for (int e = 0; e < 4; e++) o[nt][e] = 0.f;

    float m0 = -1e30f, m1 = -1e30f, l0 = 0.f, l1 = 0.f;
    const int grow0 = q0 + w16 + r;
    const int grow1 = grow0 + 8;
    const float C2 = 0.18033688f;   // 0.125 * log2(e)

    const int ktiles = blockIdx.x * 2 + 2;
    for (int kt = 0; kt < ktiles; kt++) {
        const int kbase = kt * 64;
        __syncthreads();   // all warps done reading Ks/Vs from prev iter
#pragma unroll
        for (int i = 0; i < 4; i++) {
            int idx = tid + i * 256;    // 0..1023
            int row = idx >> 4;         // 0..63
            int c4  = (idx & 15) * 4;
            float4 kv = *(const float4*)(Kb + (size_t)(kbase + row) * NHD + c4);
            float4 vv = *(const float4*)(Vb + (size_t)(kbase + row) * NHD + c4);
            uint4 u;
            u.x = f2tf32(kv.x); u.y = f2tf32(kv.y);
            u.z = f2tf32(kv.z); u.w = f2tf32(kv.w);
            *(uint4*)&Ks[row][c4] = u;
            u.x = f2tf32(vv.x); u.y = f2tf32(vv.y);
            u.z = f2tf32(vv.z); u.w = f2tf32(vv.w);
            *(uint4*)&Vs[row][c4] = u;
        }
        __syncthreads();

        // ---- S = Q @ K^T  (warp's 16 rows x 64 keys) ----
        float sfr[8][4];
#pragma unroll
        for (int nt = 0; nt < 8; nt++) {
            sfr[nt][0] = sfr[nt][1] = sfr[nt][2] = sfr[nt][3] = 0.f;
#pragma unroll
            for (int kc = 0; kc < 8; kc++) {
                uint32_t b[2];
                b[0] = Ks[nt * 8 + r][kc * 8 + c];
                b[1] = Ks[nt * 8 + r][kc * 8 + c + 4];
                mma_tf32(sfr[nt], qf[kc], b);
            }
        }

        // ---- causal mask (only diagonal tiles of this warp) ----
        if (kbase + 63 > q0 + w16) {
#pragma unroll
            for (int nt = 0; nt < 8; nt++) {
                int col = kbase + nt * 8 + 2 * c;
                if (col > grow0)     sfr[nt][0] = -1e30f;
                if (col + 1 > grow0) sfr[nt][1] = -1e30f;
                if (col > grow1)     sfr[nt][2] = -1e30f;
                if (col + 1 > grow1) sfr[nt][3] = -1e30f;
            }
        }

        // ---- online softmax ----
        float mx0 = -1e30f, mx1 = -1e30f;
#pragma unroll
        for (int nt = 0; nt < 8; nt++) {
            mx0 = fmaxf(mx0, fmaxf(sfr[nt][0], sfr[nt][1]));
            mx1 = fmaxf(mx1, fmaxf(sfr[nt][2], sfr[nt][3]));
        }
        mx0 = fmaxf(mx0, __shfl_xor_sync(0xffffffffu, mx0, 1));
        mx0 = fmaxf(mx0, __shfl_xor_sync(0xffffffffu, mx0, 2));
        mx1 = fmaxf(mx1, __shfl_xor_sync(0xffffffffu, mx1, 1));
        mx1 = fmaxf(mx1, __shfl_xor_sync(0xffffffffu, mx1, 2));

        float mn0 = fmaxf(m0, mx0);
        float mn1 = fmaxf(m1, mx1);
        float cor0 = ex2((m0 - mn0) * C2);
        float cor1 = ex2((m1 - mn1) * C2);
        l0 *= cor0; l1 *= cor1;
        m0 = mn0;   m1 = mn1;

#pragma unroll
        for (int nt = 0; nt < 8; nt++) {
            float p0 = ex2((sfr[nt][0] - mn0) * C2);
            float p1 = ex2((sfr[nt][1] - mn0) * C2);
            float p2 = ex2((sfr[nt][2] - mn1) * C2);
            float p3 = ex2((sfr[nt][3] - mn1) * C2);
            l0 += p0 + p1;
            l1 += p2 + p3;
            o[nt][0] *= cor0; o[nt][1] *= cor0;
            o[nt][2] *= cor1; o[nt][3] *= cor1;
            uint2 w0; w0.x = f2tf32(p0); w0.y = f2tf32(p1);
            *(uint2*)&Ps[w16 + r][nt * 8 + 2 * c] = w0;
            uint2 w1; w1.x = f2tf32(p2); w1.y = f2tf32(p3);
            *(uint2*)&Ps[w16 + r + 8][nt * 8 + 2 * c] = w1;
        }
        __syncwarp();   // P slab is warp-private: no CTA barrier needed

        // ---- O += P @ V ----
#pragma unroll
        for (int kc = 0; kc < 8; kc++) {
            uint32_t a[4];
            a[0] = Ps[w16 + r][kc * 8 + c];
            a[1] = Ps[w16 + r + 8][kc * 8 + c];
            a[2] = Ps[w16 + r][kc * 8 + c + 4];
            a[3] = Ps[w16 + r + 8][kc * 8 + c + 4];
#pragma unroll
            for (int nt = 0; nt < 8; nt++) {
                uint32_t b[2];
                b[0] = Vs[kc * 8 + c][nt * 8 + r];
                b[1] = Vs[kc * 8 + c + 4][nt * 8 + r];
                mma_tf32(o[nt], a, b);
            }
        }
        __syncwarp();
    }

    // ---- R5 fix: l0/l1 are per-thread partial sums over this thread's
    // columns; the true row denominator is the sum across the quad. ----
    l0 += __shfl_xor_sync(0xffffffffu, l0, 1);
    l0 += __shfl_xor_sync(0xffffffffu, l0, 2);
    l1 += __shfl_xor_sync(0xffffffffu, l1, 1);
    l1 += __shfl_xor_sync(0xffffffffu, l1, 2);

    // ---- normalize + store ----
    const int b  = bh >> 4;
    const int h  = bh & (NH - 1);
    float inv0 = 1.f / l0;
    float inv1 = 1.f / l1;
    float* y0 = g_y + ((size_t)b * NT + grow0) * ND + h * NHD;
    float* y1 = g_y + ((size_t)b * NT + grow1) * ND + h * NHD;
#pragma unroll
    for (int nt = 0; nt < 8; nt++) {
        float2 w0; w0.x = o[nt][0] * inv0; w0.y = o[nt][1] * inv0;
        *(float2*)(y0 + nt * 8 + 2 * c) = w0;
        float2 w1; w1.x = o[nt][2] * inv1; w1.y = o[nt][3] * inv1;
        *(float2*)(y1 + nt * 8 + 2 * c) = w1;
    }
}

// ---------------------------------------------------------------------------
extern "C" void kernel_launch(void* const* d_in, const int* in_sizes, int n_in,
                              void* d_out, int out_size)
{
    const float* x  = (const float*)d_in[0];
    const float* Wq = (const float*)d_in[1];
    const float* bq = (const float*)d_in[2];
    const float* Wk = (const float*)d_in[3];
    const float* bk = (const float*)d_in[4];
    const float* Wv = (const float*)d_in[5];
    const float* bv = (const float*)d_in[6];
    const float* Wp = (const float*)d_in[7];
    const float* bp = (const float*)d_in[8];
    float* out = (float*)d_out;

    cudaFuncSetAttribute(attn_tc_kernel,
                         cudaFuncAttributeMaxDynamicSharedMemorySize,
                         ATTN_SMEM);

    dim3 gq(ND / 128, NM / 128, 3);   // 8 x 32 x 3
    gemm_kernel<true><<<gq, 256>>>(x, Wq, bq, Wk, bk, Wv, bv, nullptr);

    dim3 ga(NT / 128, NB * NH);       // 16 x 32
    attn_tc_kernel<<<ga, 256, ATTN_SMEM>>>();

    dim3 gp(ND / 128, NM / 128, 1);   // 8 x 32
    gemm_kernel<false><<<gp, 256>>>(nullptr, Wp, bp, nullptr, nullptr,
                                    nullptr, nullptr, out);
}